// round 4
// baseline (speedup 1.0000x reference)
#include <cuda_runtime.h>
#include <cstdint>

#define NB 16
#define TT 128
#define VV 64
#define FF 16
#define TCH 8                    // timesteps per smem chunk
#define NCH (TT / TCH)           // 16 chunks
#define PADF 20                  // padded feature stride (80B, 16B-aligned)
#define JPB 8                    // j-columns per CTA

// ---------------------------------------------------------------------------
// Fully fused kernel. CTA = (n, 8 j-columns). 512 threads = 64 i-lanes x 8
// t-groups. Streams x[n] through one 40KB smem tile (16 chunks x 8 timesteps)
// with register prefetch. Each thread accumulates a[f]*|x[t,i,f]-x[t,j,f]|
// over its t-subset for (i, 8 j) in packed-f32x2 registers. Epilogue combines
// t-groups in (reused) smem, applies exp(relu(mean)), column-normalizes over
// i, and writes out[n,i,j]. No scratch gmem, no second kernel.
// ---------------------------------------------------------------------------
__global__ __launch_bounds__(512, 1) void gl_fused_kernel(
    const float* __restrict__ x, const float* __restrict__ a,
    float* __restrict__ out)
{
    __shared__ __align__(16) float tile[TCH][VV][PADF];   // 40 KB (reused as part[])
    __shared__ float E[JPB][VV + 1];
    __shared__ float cinv[JPB];

    const int n     = blockIdx.y;
    const int jbase = blockIdx.x * JPB;
    const int tid   = threadIdx.x;
    const int i     = tid & 63;
    const int tg    = tid >> 6;       // t-group 0..7

    // Pack a[f] coefficient pairs into f32x2 (low 32 bits = even f).
    uint64_t af2[8];
#pragma unroll
    for (int k = 0; k < 8; k++) {
        af2[k] = (uint64_t)__float_as_uint(__ldg(&a[2 * k])) |
                 ((uint64_t)__float_as_uint(__ldg(&a[2 * k + 1])) << 32);
    }

    const float4* src = (const float4*)(x + (size_t)n * TT * VV * FF);

    // Prefetch chunk 0 into registers (4 x LDG.128 per thread).
    float4 pre[4];
#pragma unroll
    for (int k = 0; k < 4; k++) pre[k] = src[tid + k * 512];

    uint64_t acc[JPB];
#pragma unroll
    for (int jj = 0; jj < JPB; jj++) acc[jj] = 0ull;

#pragma unroll 1
    for (int c = 0; c < NCH; c++) {
        __syncthreads();              // previous chunk's consumers done
#pragma unroll
        for (int k = 0; k < 4; k++) {
            int q  = tid + k * 512;
            int t  = q >> 8;          // 256 float4 per timestep
            int r  = q & 255;
            int vv = r >> 2;
            int f4 = r & 3;
            *(float4*)&tile[t][vv][f4 * 4] = pre[k];
        }
        __syncthreads();
        if (c + 1 < NCH) {            // prefetch next chunk (overlaps compute)
#pragma unroll
            for (int k = 0; k < 4; k++)
                pre[k] = src[(c + 1) * 2048 + tid + k * 512];
        }

        // This thread's timestep within the chunk is tg.
        // Register-cache i-row, pre-negated so inner loop uses add2 not sub.
        const ulonglong2* zr = (const ulonglong2*)&tile[tg][i][0];
        ulonglong2 zi0 = zr[0], zi1 = zr[1], zi2 = zr[2], zi3 = zr[3];
        uint64_t nzi[8];
        nzi[0] = zi0.x ^ 0x8000000080000000ULL;
        nzi[1] = zi0.y ^ 0x8000000080000000ULL;
        nzi[2] = zi1.x ^ 0x8000000080000000ULL;
        nzi[3] = zi1.y ^ 0x8000000080000000ULL;
        nzi[4] = zi2.x ^ 0x8000000080000000ULL;
        nzi[5] = zi2.y ^ 0x8000000080000000ULL;
        nzi[6] = zi3.x ^ 0x8000000080000000ULL;
        nzi[7] = zi3.y ^ 0x8000000080000000ULL;

#pragma unroll
        for (int jj = 0; jj < JPB; jj++) {
            // j-row is warp-uniform (tg uniform, jj compile-time): LDS broadcast.
            const ulonglong2* zjr = (const ulonglong2*)&tile[tg][jbase + jj][0];
            ulonglong2 q0 = zjr[0], q1 = zjr[1], q2 = zjr[2], q3 = zjr[3];
            uint64_t zj[8] = {q0.x, q0.y, q1.x, q1.y, q2.x, q2.y, q3.x, q3.y};
#pragma unroll
            for (int p = 0; p < 8; p++) {
                uint64_t d;
                asm("add.rn.f32x2 %0, %1, %2;"
                    : "=l"(d) : "l"(nzi[p]), "l"(zj[p]));
                d &= 0x7FFFFFFF7FFFFFFFULL;           // packed |d| (2x LOP3)
                asm("fma.rn.f32x2 %0, %1, %2, %3;"
                    : "=l"(acc[jj]) : "l"(af2[p]), "l"(d), "l"(acc[jj]));
            }
        }
    }

    // ---- Epilogue: combine 8 t-groups, exp(relu(mean)), normalize over i ----
    __syncthreads();                  // done reading tile; reuse as part[]
    float* part = (float*)tile;       // part[tg][i][9] : stride 9 -> conflict-free
#pragma unroll
    for (int jj = 0; jj < JPB; jj++) {
        float r = __uint_as_float((unsigned)acc[jj]) +
                  __uint_as_float((unsigned)(acc[jj] >> 32));
        part[((size_t)tg * VV + i) * 9 + jj] = r;
    }
    __syncthreads();

    {   // thread -> (i2, jj2); sum the 8 t-group partials
        const int i2  = tid & 63;
        const int jj2 = tid >> 6;
        float s = 0.f;
#pragma unroll
        for (int g = 0; g < 8; g++)
            s += part[((size_t)g * VV + i2) * 9 + jj2];
        E[jj2][i2] = expf(fmaxf(s * (1.0f / (float)TT), 0.f));
    }
    __syncthreads();

    {   // warps 0..7: column sum over all 64 i for column w
        const int w = tid >> 5, lane = tid & 31;
        if (w < JPB) {
            float v = E[w][lane] + E[w][lane + 32];
#pragma unroll
            for (int o = 16; o; o >>= 1) v += __shfl_xor_sync(0xffffffffu, v, o);
            if (lane == 0) cinv[w] = 1.0f / v;
        }
    }
    __syncthreads();

    {   // write out[n][io][jbase+jo]; 8 consecutive floats per io (32B stores)
        const int io = tid >> 3;
        const int jo = tid & 7;
        out[(size_t)n * VV * VV + io * VV + jbase + jo] = E[jo][io] * cinv[jo];
    }
}

extern "C" void kernel_launch(void* const* d_in, const int* in_sizes, int n_in,
                              void* d_out, int out_size)
{
    const float* x = (const float*)d_in[0];       // [16,128,64,16] fp32
    const float* a = (const float*)d_in[1];       // [16,1] fp32
    float* out = (float*)d_out;                   // [16,64,64] fp32

    gl_fused_kernel<<<dim3(VV / JPB, NB), 512>>>(x, a, out);
}